// round 1
// baseline (speedup 1.0000x reference)
#include <cuda_runtime.h>
#include <math.h>

#define Bn 128
#define Tn 1024
#define Hn 512

// Grid-barrier counter for the persistent RNN kernel.
__device__ unsigned g_count;

__global__ void zero_bar() { g_count = 0u; }

// ---------------------------------------------------------------------------
// Phase 1: pre[t][b][:] = X[b][t][:] @ Wx + bias   (written into d_out, [T,B,H])
// Classic smem-tiled fp32 GEMM: BM=128, BN=64, BK=16, 256 threads, 8x4 / thread.
// ---------------------------------------------------------------------------
__global__ __launch_bounds__(256) void gemm_xw(
    const float* __restrict__ X,    // [B*T, H] rows r = b*T + t
    const float* __restrict__ Wx,   // [H, H]
    const float* __restrict__ bias, // [H]
    float* __restrict__ out)        // [T, B, H]
{
    __shared__ float As[16][132];   // [k][row], padded (132*4=528B, 16B-aligned rows)
    __shared__ float Bs[16][68];    // [k][col], padded (68*4=272B, 16B-aligned rows)

    const int bm0 = blockIdx.y * 128;
    const int bn0 = blockIdx.x * 64;
    const int tid = threadIdx.x;
    const int tr  = (tid >> 4) << 3;  // row offset in tile: 0..120 step 8
    const int tc  = (tid & 15) << 2;  // col offset in tile: 0..60 step 4

    float acc[8][4];
#pragma unroll
    for (int i = 0; i < 8; i++)
#pragma unroll
        for (int j = 0; j < 4; j++) acc[i][j] = 0.0f;

    for (int k0 = 0; k0 < Hn; k0 += 16) {
        // Load A tile: 128 rows x 16 k = 512 float4; each thread loads 2.
#pragma unroll
        for (int v = 0; v < 2; v++) {
            int f   = tid + (v << 8);
            int row = f >> 2;           // 0..127
            int kk  = (f & 3) << 2;     // 0,4,8,12
            float4 a = *(const float4*)(X + (size_t)(bm0 + row) * Hn + k0 + kk);
            As[kk + 0][row] = a.x;
            As[kk + 1][row] = a.y;
            As[kk + 2][row] = a.z;
            As[kk + 3][row] = a.w;
        }
        // Load B tile: 16 k x 64 cols = 256 float4; one per thread.
        {
            int kk  = tid >> 4;
            int col = (tid & 15) << 2;
            *(float4*)&Bs[kk][col] =
                *(const float4*)(Wx + (size_t)(k0 + kk) * Hn + bn0 + col);
        }
        __syncthreads();

#pragma unroll
        for (int kk = 0; kk < 16; kk++) {
            float4 a0 = *(const float4*)&As[kk][tr];
            float4 a1 = *(const float4*)&As[kk][tr + 4];
            float4 b0 = *(const float4*)&Bs[kk][tc];
            float av[8] = {a0.x, a0.y, a0.z, a0.w, a1.x, a1.y, a1.z, a1.w};
            float bv[4] = {b0.x, b0.y, b0.z, b0.w};
#pragma unroll
            for (int i = 0; i < 8; i++)
#pragma unroll
                for (int j = 0; j < 4; j++)
                    acc[i][j] = fmaf(av[i], bv[j], acc[i][j]);
        }
        __syncthreads();
    }

    float4 bb = *(const float4*)(bias + bn0 + tc);
#pragma unroll
    for (int i = 0; i < 8; i++) {
        int m = bm0 + tr + i;       // row in [B*T): m = b*T + t
        int b = m >> 10;            // T = 1024
        int t = m & 1023;
        float4 o;
        o.x = acc[i][0] + bb.x;
        o.y = acc[i][1] + bb.y;
        o.z = acc[i][2] + bb.z;
        o.w = acc[i][3] + bb.w;
        *(float4*)(out + ((size_t)t * Bn + b) * Hn + bn0 + tc) = o;
    }
}

// ---------------------------------------------------------------------------
// Phase 2: persistent kernel, 1024 sequential steps with a grid barrier.
//   out[t] = tanh(out[t](pre) + prev_state @ Wh)  updated in place.
// 128 CTAs = 16 row-groups (8 B-rows) x 8 col-groups (64 H-cols).
// Wh columns for this col-group live in smem for the WHOLE kernel (128 KB).
// Per step only the 8x512 state slice is (re)loaded from global.
// ---------------------------------------------------------------------------
__global__ __launch_bounds__(128) void rnn_steps(
    const float* __restrict__ state0,  // [B, H]
    const float* __restrict__ Wh,      // [H, H]
    float* __restrict__ out)           // [T, B, H] (holds pre on entry)
{
    extern __shared__ float sm[];
    float* Whs = sm;                 // [512][64]  (k-major, c contiguous)
    float* Ss  = sm + 512 * 64;      // [8][512]   (row-major, k contiguous)

    const int cg  = blockIdx.x & 7;   // column group 0..7
    const int rg  = blockIdx.x >> 3;  // row group    0..15
    const int c0  = cg * 64;
    const int r0  = rg * 8;
    const int tid = threadIdx.x;

    // Load Wh[:, c0:c0+64] into smem once (8192 float4, 64 per thread).
#pragma unroll 4
    for (int i = 0; i < 64; i++) {
        int f = tid + i * 128;        // float4 index 0..8191
        int k = f >> 4;               // 0..511
        int c = (f & 15) << 2;        // 0..60
        *(float4*)&Whs[k * 64 + c] =
            *(const float4*)(Wh + (size_t)k * Hn + c0 + c);
    }

    const int rl = tid >> 4;          // local row 0..7
    const int tc = (tid & 15) << 2;   // local col 0..60 step 4
    const float* srow = &Ss[rl * 512];

    for (int t = 0; t < Tn; t++) {
        const float* prev = (t == 0) ? state0
                                     : (out + (size_t)(t - 1) * Bn * Hn);
        // Load state rows [r0, r0+8) x [0,512) into smem (1024 float4).
#pragma unroll
        for (int i = 0; i < 8; i++) {
            int f = tid + i * 128;     // float4 index 0..1023
            int r = f >> 7;            // 0..7
            int k = (f & 127) << 2;    // 0..508
            *(float4*)&Ss[r * 512 + k] =
                *(const float4*)(prev + (size_t)(r0 + r) * Hn + k);
        }
        __syncthreads();

        float acc0 = 0.f, acc1 = 0.f, acc2 = 0.f, acc3 = 0.f;
#pragma unroll 4
        for (int k = 0; k < 512; k += 4) {
            float4 sv = *(const float4*)(srow + k);
            float4 w0 = *(const float4*)&Whs[(k + 0) * 64 + tc];
            float4 w1 = *(const float4*)&Whs[(k + 1) * 64 + tc];
            float4 w2 = *(const float4*)&Whs[(k + 2) * 64 + tc];
            float4 w3 = *(const float4*)&Whs[(k + 3) * 64 + tc];
            acc0 = fmaf(sv.x, w0.x, acc0);
            acc1 = fmaf(sv.x, w0.y, acc1);
            acc2 = fmaf(sv.x, w0.z, acc2);
            acc3 = fmaf(sv.x, w0.w, acc3);
            acc0 = fmaf(sv.y, w1.x, acc0);
            acc1 = fmaf(sv.y, w1.y, acc1);
            acc2 = fmaf(sv.y, w1.z, acc2);
            acc3 = fmaf(sv.y, w1.w, acc3);
            acc0 = fmaf(sv.z, w2.x, acc0);
            acc1 = fmaf(sv.z, w2.y, acc1);
            acc2 = fmaf(sv.z, w2.z, acc2);
            acc3 = fmaf(sv.z, w2.w, acc3);
            acc0 = fmaf(sv.w, w3.x, acc0);
            acc1 = fmaf(sv.w, w3.y, acc1);
            acc2 = fmaf(sv.w, w3.z, acc2);
            acc3 = fmaf(sv.w, w3.w, acc3);
        }

        float* op = out + (size_t)t * Bn * Hn + (size_t)(r0 + rl) * Hn + c0 + tc;
        float4 pre = *(const float4*)op;
        float4 o;
        o.x = tanhf(pre.x + acc0);
        o.y = tanhf(pre.y + acc1);
        o.z = tanhf(pre.z + acc2);
        o.w = tanhf(pre.w + acc3);
        *(float4*)op = o;

        if (t != Tn - 1) {
            // Grid barrier: drain stores to L2, arrive, spin, acquire.
            __threadfence();
            __syncthreads();
            if (tid == 0) {
                atomicAdd(&g_count, 1u);
                const unsigned target = 128u * (unsigned)(t + 1);
                while (*(volatile unsigned*)&g_count < target) { }
                __threadfence();
            }
            __syncthreads();
        }
    }
}

extern "C" void kernel_launch(void* const* d_in, const int* in_sizes, int n_in,
                              void* d_out, int out_size)
{
    const float* X    = (const float*)d_in[0];  // inputs_tensor [B,T,H]
    const float* S0   = (const float*)d_in[1];  // state_tensor  [1,B,H]
    const float* Wx   = (const float*)d_in[2];  // [H,H]
    const float* Wh   = (const float*)d_in[3];  // [H,H]
    const float* bias = (const float*)d_in[4];  // [H]
    float* out = (float*)d_out;                 // [T,B,H]

    (void)in_sizes; (void)n_in; (void)out_size;

    const int dyn_smem = (512 * 64 + 8 * 512) * (int)sizeof(float);  // 147456
    cudaFuncSetAttribute(rnn_steps,
                         cudaFuncAttributeMaxDynamicSharedMemorySize, dyn_smem);

    zero_bar<<<1, 1>>>();

    dim3 g1(Hn / 64, (Bn * Tn) / 128);  // (8, 1024)
    gemm_xw<<<g1, 256>>>(X, Wx, bias, out);

    rnn_steps<<<128, 128, dyn_smem>>>(S0, Wh, out);
}